// round 16
// baseline (speedup 1.0000x reference)
#include <cuda_runtime.h>
#include <cstdint>

// ============================================================
// SVDDecomposeTransMatrix — round 15: single fused kernel.
//   Phase 1: blocks 0-3 all-smem Horner Cayley (k<8) + compose
//            -> g_ML, g_MR (both natural row-major); others L2-prefetch.
//   Phase 2: out^T = (MR^T @ Xs^T) @ ML.
//     GEMM1: A=MR^T const regs, B=Xs^T via natural-layout reads (stride 68).
//     Transpose U: accumulators -> A-frags via shfl (no smem roundtrip!).
//     GEMM2: A=U regs, B=ML from smem (stride 72). One barrier per tile.
// ============================================================

#define PSTR 68   // prep smem stride
#define XSTR 68   // Xs smem stride (conflict-free transposed-pattern reads)
#define MSTR2 72  // sML smem stride (conflict-free standard-pattern reads)
#define NBLK 456  // 152 SMs * 3 CTAs -> all resident (spins are safe)

__device__ float g_Qv[2][4096];   // Cayley(v_left), Cayley(v_right)
__device__ float g_ML[4096];      // m_left  natural: g_ML[i*64+l]
__device__ float g_MR[4096];      // m_right natural: g_MR[j*64+r]
__device__ int   g_qdone[2];
__device__ int   g_mdone;
__device__ int   g_passed;
__device__ unsigned g_work;

__device__ __forceinline__ int ld_acquire(const int* p) {
    int v; asm volatile("ld.acquire.gpu.b32 %0, [%1];" : "=r"(v) : "l"(p)); return v;
}
__device__ __forceinline__ int ld_relaxed(const int* p) {
    int v; asm volatile("ld.relaxed.gpu.b32 %0, [%1];" : "=r"(v) : "l"(p)); return v;
}

// C = A*B (+B if ADD), 64x64 all stride PSTR, 128 threads, 4x8 tiles.
template <bool ADD>
__device__ __forceinline__ void mm128(const float* __restrict__ A,
                                      const float* __restrict__ B,
                                      float* __restrict__ C, int tid) {
    int r0 = (tid >> 3) * 4;
    int c0 = (tid & 7) * 8;
    float acc[4][8];
#pragma unroll
    for (int i = 0; i < 4; ++i)
#pragma unroll
        for (int j = 0; j < 8; ++j) acc[i][j] = 0.f;
#pragma unroll 4
    for (int k = 0; k < 64; ++k) {
        float4 bl = *(const float4*)&B[k * PSTR + c0];
        float4 bh = *(const float4*)&B[k * PSTR + c0 + 4];
        float bv[8] = {bl.x, bl.y, bl.z, bl.w, bh.x, bh.y, bh.z, bh.w};
#pragma unroll
        for (int i = 0; i < 4; ++i) {
            float a = A[(r0 + i) * PSTR + k];
#pragma unroll
            for (int j = 0; j < 8; ++j) acc[i][j] += a * bv[j];
        }
    }
#pragma unroll
    for (int i = 0; i < 4; ++i) {
        if (ADD) {
#pragma unroll
            for (int j = 0; j < 8; ++j) acc[i][j] += B[(r0 + i) * PSTR + c0 + j];
        }
        *(float4*)&C[(r0 + i) * PSTR + c0]     = make_float4(acc[i][0], acc[i][1], acc[i][2], acc[i][3]);
        *(float4*)&C[(r0 + i) * PSTR + c0 + 4] = make_float4(acc[i][4], acc[i][5], acc[i][6], acc[i][7]);
    }
}

__device__ __forceinline__ unsigned f2tf(float f) {
    unsigned u; asm("cvt.rna.tf32.f32 %0, %1;" : "=r"(u) : "f"(f)); return u;
}

__device__ __forceinline__ void mma_tf32(float& d0, float& d1, float& d2, float& d3,
                                         unsigned a0, unsigned a1, unsigned a2, unsigned a3,
                                         unsigned b0, unsigned b1) {
    asm volatile(
        "mma.sync.aligned.m16n8k8.row.col.f32.tf32.tf32.f32 "
        "{%0,%1,%2,%3}, {%4,%5,%6,%7}, {%8,%9}, {%0,%1,%2,%3};\n"
        : "+f"(d0), "+f"(d1), "+f"(d2), "+f"(d3)
        : "r"(a0), "r"(a1), "r"(a2), "r"(a3), "r"(b0), "r"(b1));
}

__global__ __launch_bounds__(128, 3)
void fused_kernel(const float* __restrict__ x,
                  const float* __restrict__ u_left,
                  const float* __restrict__ v_left,
                  const float* __restrict__ diag_left,
                  const float* __restrict__ u_right,
                  const float* __restrict__ v_right,
                  const float* __restrict__ diag_right,
                  const float* __restrict__ diag_scale,
                  float* __restrict__ out, int ntiles) {
    extern __shared__ float sm[];
    __shared__ unsigned sp;
    int tid = threadIdx.x, bid = blockIdx.x;

    // ========== PHASE 1: prep (blocks 0-3) / L2 prefetch (others) ==========
    if (bid < 4) {
        float* s0 = sm;                  // starts = B
        float* s1 = s0 + 64 * PSTR;      // starts = I+B
        float* s2 = s1 + 64 * PSTR;
        const float* X = (bid == 0) ? u_left : (bid == 1) ? v_left :
                         (bid == 2) ? u_right : v_right;
        for (int idx = tid; idx < 4096; idx += 128) {
            int i = idx >> 6, j = idx & 63;
            float a = (i > j) ? X[i * 64 + j] : (i < j ? -X[j * 64 + i] : 0.f);
            float b = 0.5f * a;
            s0[i * PSTR + j] = b;
            s1[i * PSTR + j] = (i == j) ? 1.f + b : b;
        }
        __syncthreads();
        mm128<true >(s0, s1, s2, tid);   // s2 = (I+B)(I+B)
        __syncthreads();
        mm128<false>(s0, s0, s1, tid);   // s1 = B^2
        __syncthreads();
        mm128<true >(s1, s2, s0, tid);   // s0 = (I+B^2)s2
        __syncthreads();
        mm128<false>(s1, s1, s2, tid);   // s2 = B^4
        __syncthreads();
        mm128<true >(s2, s0, s1, tid);   // s1 = Q = (I+B^4)s0
        __syncthreads();

        if (bid == 1 || bid == 3) {
            float* dst = g_Qv[bid >> 1];
            for (int idx = tid; idx < 4096; idx += 128) {
                int i = idx >> 6, j = idx & 63;
                dst[idx] = s1[i * PSTR + j];
            }
            __threadfence();
            __syncthreads();
            if (tid == 0) atomicExch(&g_qdone[bid >> 1], 1);
        } else {
            if (tid == 0) { while (ld_acquire(&g_qdone[bid >> 1]) == 0) __nanosleep(64); }
            __syncthreads();
            const float* Qv = g_Qv[bid >> 1];
            const float* d  = (bid == 0) ? diag_left : diag_right;
            for (int idx = tid; idx < 4096; idx += 128) {
                int i = idx >> 6, j = idx & 63;
                s2[i * PSTR + j] = d[i] * Qv[idx];    // D = diag * Q_v
            }
            __syncthreads();
            mm128<false>(s1, s2, s0, tid);            // M = Q_u @ D  -> s0
            __syncthreads();
            for (int idx = tid; idx < 4096; idx += 128) {
                int a = idx >> 6, b = idx & 63;
                float v = s0[a * PSTR + b];
                if (bid == 0) g_ML[idx] = v;          // natural [i][l]
                else          g_MR[idx] = v;          // natural [j][r]
            }
            __syncthreads();
            if (tid == 0) {
                atomicExch(&g_qdone[bid >> 1], 0);    // self-reset for replay
                if (bid == 0) g_work = 0;             // queue reset before release
                __threadfence();
                atomicAdd(&g_mdone, 1);
            }
        }
    } else {
        const char* xb = (const char*)x;
        for (int q = bid; q < ntiles; q += NBLK) {
            if (ld_relaxed(&g_mdone) >= 2) break;
            const char* pc = xb + (size_t)q * 16384 + tid * 128;
            asm volatile("prefetch.global.L2 [%0];" :: "l"(pc));
        }
    }

    // ========== barrier on prep completion (+ flag recycling) ==========
    if (tid == 0) {
        while (ld_acquire(&g_mdone) < 2) __nanosleep(32);
        int old = atomicAdd(&g_passed, 1);
        if (old == NBLK - 1) {
            atomicExch(&g_mdone, 0);
            atomicExch(&g_passed, 0);
        }
    }
    __syncthreads();

    // ========== PHASE 2: out^T = (MR^T @ Xs^T) @ ML ==========
    float* sDiag = sm;                       // 4096 fp32
    float* sX0   = sm + 4096;                // 64*XSTR
    float* sX1   = sX0 + 64 * XSTR;          // 64*XSTR
    float* sML   = sX1 + 64 * XSTR;          // 64*MSTR2 (ML natural, tf32)

    int warp = tid >> 5, lane = tid & 31;
    int g = lane >> 2, t4 = lane & 3;
    int strip = warp * 16;                   // warp's 16 r-rows
    int b = t4 & 1;
    int srcLo = 4 * g + (t4 >> 1);           // shfl sources for transpose
    int srcHi = srcLo + 2;

    for (int i = tid; i < 4096; i += 128) {
        sDiag[i] = diag_scale[i];
        int r = i >> 6, c = i & 63;
        sML[r * MSTR2 + c] = __uint_as_float(f2tf(g_ML[i]));   // [i][l]
    }
    // GEMM1 A-frags: A = MR^T (m=r, k=j) = g_MR[j*64 + r]
    unsigned a1f[8][4];
#pragma unroll
    for (int kk = 0; kk < 8; ++kk) {
        int j0 = kk * 8 + t4;
        a1f[kk][0] = f2tf(g_MR[j0       * 64 + strip + g]);
        a1f[kk][1] = f2tf(g_MR[j0       * 64 + strip + g + 8]);
        a1f[kk][2] = f2tf(g_MR[(j0 + 4) * 64 + strip + g]);
        a1f[kk][3] = f2tf(g_MR[(j0 + 4) * 64 + strip + g + 8]);
    }
    if (tid == 0) sp = atomicAdd(&g_work, 1u);
    __syncthreads();

    int t = (int)sp, cur = 0;
    float4 pf[8];
    if (t < ntiles) {
        const float4* xt = (const float4*)(x + (size_t)t * 4096);
#pragma unroll
        for (int it = 0; it < 8; ++it) pf[it] = xt[it * 128 + tid];
    }

    const float4* dg = (const float4*)sDiag;
    while (t < ntiles) {
        float* sXs = cur ? sX1 : sX0;
        // ---- stage Xs = x_tile * diag_scale (tf32 bits) ----
#pragma unroll
        for (int it = 0; it < 8; ++it) {
            int idx = it * 128 + tid;
            float4 v = pf[it];
            float4 s = dg[idx];
            uint4 pk = make_uint4(f2tf(v.x * s.x), f2tf(v.y * s.y),
                                  f2tf(v.z * s.z), f2tf(v.w * s.w));
            int row = idx >> 4, col = (idx & 15) << 2;
            *(uint4*)&sXs[row * XSTR + col] = pk;
        }
        if (tid == 0) sp = atomicAdd(&g_work, 1u);
        __syncthreads();   // SYNC: staging + sp visible; GEMM1(i-1) reads done
        int tn = (int)sp;

        // ---- issue next tile's loads early ----
        if (tn < ntiles) {
            const float4* xtn = (const float4*)(x + (size_t)tn * 4096);
#pragma unroll
            for (int it = 0; it < 8; ++it) pf[it] = xtn[it * 128 + tid];
        }

        // ---- GEMM1: U[r,i] = MR^T @ Xs^T  (B from Xs natural layout) ----
        float c1[8][4];
#pragma unroll
        for (int nn = 0; nn < 8; ++nn) {
            c1[nn][0] = 0.f; c1[nn][1] = 0.f; c1[nn][2] = 0.f; c1[nn][3] = 0.f;
#pragma unroll
            for (int kk = 0; kk < 8; ++kk) {
                unsigned b0 = __float_as_uint(sXs[(nn * 8 + g) * XSTR + kk * 8 + t4]);
                unsigned b1 = __float_as_uint(sXs[(nn * 8 + g) * XSTR + kk * 8 + t4 + 4]);
                mma_tf32(c1[nn][0], c1[nn][1], c1[nn][2], c1[nn][3],
                         a1f[kk][0], a1f[kk][1], a1f[kk][2], a1f[kk][3], b0, b1);
            }
        }

        // ---- transpose U: C-layout -> A-frags via shfl (warp-local) ----
        // dest lane (g,t4) wants U[m=g(+8)][k=t4(+4)] of k-block kk = C-block nn=kk
        unsigned a2[8][4];
#pragma unroll
        for (int kk = 0; kk < 8; ++kk) {
            float v00 = __shfl_sync(0xffffffffu, c1[kk][0], srcLo);
            float v01 = __shfl_sync(0xffffffffu, c1[kk][1], srcLo);
            float v10 = __shfl_sync(0xffffffffu, c1[kk][2], srcLo);
            float v11 = __shfl_sync(0xffffffffu, c1[kk][3], srcLo);
            float v20 = __shfl_sync(0xffffffffu, c1[kk][0], srcHi);
            float v21 = __shfl_sync(0xffffffffu, c1[kk][1], srcHi);
            float v30 = __shfl_sync(0xffffffffu, c1[kk][2], srcHi);
            float v31 = __shfl_sync(0xffffffffu, c1[kk][3], srcHi);
            a2[kk][0] = f2tf(b ? v01 : v00);   // U[g,   t4]
            a2[kk][1] = f2tf(b ? v11 : v10);   // U[g+8, t4]
            a2[kk][2] = f2tf(b ? v21 : v20);   // U[g,   t4+4]
            a2[kk][3] = f2tf(b ? v31 : v30);   // U[g+8, t4+4]
        }

        // ---- GEMM2: out^T[r,l] = U @ ML  (B from sML, conflict-free) ----
        float* ot = out + (size_t)t * 4096;
#pragma unroll
        for (int nn = 0; nn < 8; ++nn) {
            float c0 = 0.f, c1v = 0.f, c2 = 0.f, c3 = 0.f;
#pragma unroll
            for (int kk = 0; kk < 8; ++kk) {
                unsigned b0 = __float_as_uint(sML[(kk * 8 + t4)     * MSTR2 + nn * 8 + g]);
                unsigned b1 = __float_as_uint(sML[(kk * 8 + t4 + 4) * MSTR2 + nn * 8 + g]);
                mma_tf32(c0, c1v, c2, c3,
                         a2[kk][0], a2[kk][1], a2[kk][2], a2[kk][3], b0, b1);
            }
            int r = strip + g;
            int l0 = nn * 8 + 2 * t4;
            ot[l0 * 64 + r]           = c0;
            ot[(l0 + 1) * 64 + r]     = c1v;
            ot[l0 * 64 + r + 8]       = c2;
            ot[(l0 + 1) * 64 + r + 8] = c3;
        }
        t = tn; cur ^= 1;
    }
}

// ---------------- launch ----------------
extern "C" void kernel_launch(void* const* d_in, const int* in_sizes, int n_in,
                              void* d_out, int out_size) {
    const float* x          = (const float*)d_in[0];
    const float* u_left     = (const float*)d_in[1];
    const float* v_left     = (const float*)d_in[2];
    const float* diag_left  = (const float*)d_in[3];
    const float* u_right    = (const float*)d_in[4];
    const float* v_right    = (const float*)d_in[5];
    const float* diag_right = (const float*)d_in[6];
    const float* diag_scale = (const float*)d_in[7];
    float* out = (float*)d_out;

    int ntiles = in_sizes[0] / 4096;

    // smem = max(prep 3*64*68=13056, kron 4096+2*64*68+64*72=17408) floats
    //      = 17408 * 4 = 69632 B; x3 CTAs = 208.9KB <= 227KB
    const int SMEM_BYTES = (4096 + 2 * 64 * XSTR + 64 * MSTR2) * (int)sizeof(float);
    cudaFuncSetAttribute(fused_kernel, cudaFuncAttributeMaxDynamicSharedMemorySize, SMEM_BYTES);

    fused_kernel<<<NBLK, 128, SMEM_BYTES>>>(x, u_left, v_left, diag_left,
                                            u_right, v_right, diag_right,
                                            diag_scale, out, ntiles);
}